// round 17
// baseline (speedup 1.0000x reference)
#include <cuda_runtime.h>
#include <cuda_bf16.h>
#include <math.h>
#include <stddef.h>
#include <stdint.h>

#define TT 512
#define BB 32
#define HH 256
#define NSTEP 64

// ---------------- scratch (static device arrays; no allocations) ----------------
__device__ float g_gx[(size_t)TT * BB * 2048];                     // x@Wih^T + b, both dirs
__device__ __align__(16) __nv_bfloat16 g_A2[(size_t)16384 * 3072]; // [Ahi | Ahi | Alo]
__device__ __align__(16) __nv_bfloat16 g_W2[(size_t)2048 * 3072];  // [Whi | Wlo | Whi]
__device__ float g_h[2][2 * BB * HH];
__device__ float g_c[2 * BB * HH];
__device__ float g_dh0[2][BB * HH];
__device__ float g_dh1[2][BB * HH];
__device__ unsigned g_cnt[4];                 // monotonic barrier counters (memset per replay)

__device__ __forceinline__ float sigf(float x) { return 1.0f / (1.0f + expf(-x)); }

__device__ __forceinline__ uint32_t smem_u32(const void* p) {
    return (uint32_t)__cvta_generic_to_shared(p);
}
#define SMEM_SWIZZLE_128B(b) ((b) ^ (((b) >> 3) & 0x70))

// Monotonic-counter grid barrier among co-resident blocks.
// Release = acq_rel fence + one L2 RMW; consumers poll the counter.
__device__ __forceinline__ void gridbar_inc(int id, unsigned target) {
    asm volatile("fence.acq_rel.gpu;" ::: "memory");
    __syncthreads();
    if (threadIdx.x == 0) {
        atomicAdd(&g_cnt[id], 1u);
        volatile unsigned* cp = (volatile unsigned*)&g_cnt[id];
        while (*cp < target) { }
    }
    __syncthreads();
}

// ---------------- Phase 0: fp32 -> bf16 hi/lo split ----------------
__device__ __forceinline__ void split4(float4 v, uint2& hp, uint2& lp) {
    float f[4] = {v.x, v.y, v.z, v.w};
    unsigned short hu[4], lu[4];
#pragma unroll
    for (int j = 0; j < 4; j++) {
        __nv_bfloat16 h = __float2bfloat16(f[j]);
        float hf = __bfloat162float(h);
        __nv_bfloat16 l = __float2bfloat16(f[j] - hf);   // x - hi exact in fp32
        hu[j] = *(unsigned short*)&h;
        lu[j] = *(unsigned short*)&l;
    }
    hp.x = hu[0] | ((unsigned)hu[1] << 16); hp.y = hu[2] | ((unsigned)hu[3] << 16);
    lp.x = lu[0] | ((unsigned)lu[1] << 16); lp.y = lu[2] | ((unsigned)lu[3] << 16);
}

__global__ void __launch_bounds__(256) conv_a(const float* __restrict__ X) {
    size_t i = (size_t)blockIdx.x * 256 + threadIdx.x;
    float4 v = ((const float4*)X)[i];
    size_t e = i << 2;
    size_t m = e >> 10;
    int k = (int)(e & 1023);
    uint2 hp, lp;
    split4(v, hp, lp);
    __nv_bfloat16* rp = g_A2 + m * 3072 + k;
    *(uint2*)(rp)        = hp;
    *(uint2*)(rp + 1024) = hp;
    *(uint2*)(rp + 2048) = lp;
}

__global__ void __launch_bounds__(256) conv_w(const float* __restrict__ Wf, const float* __restrict__ Wb) {
    size_t i = (size_t)blockIdx.x * 256 + threadIdx.x;
    size_t e = i << 2;
    size_t n = e >> 10;
    int k = (int)(e & 1023);
    const float* src = (n < 1024) ? (Wf + n * 1024 + k) : (Wb + (n - 1024) * 1024 + k);
    float4 v = *(const float4*)src;
    uint2 hp, lp;
    split4(v, hp, lp);
    __nv_bfloat16* rp = g_W2 + n * 3072 + k;
    *(uint2*)(rp)        = hp;
    *(uint2*)(rp + 1024) = lp;
    *(uint2*)(rp + 2048) = hp;
}

// ---------------- Phase 1: HMMA bf16 GEMM (128x128 tile, 2 CTAs/SM) ----------------
#define SM_A0 0
#define SM_A1 16384
#define SM_B0 32768
#define SM_B1 49152
#define GEMM_SMEM 65536
#define NC 48

__device__ __forceinline__ void cp16(uint32_t dst, const void* src) {
    asm volatile("cp.async.cg.shared.global [%0], [%1], 16;" :: "r"(dst), "l"(src));
}

__global__ void __launch_bounds__(256, 2) gemm_mma(const float* __restrict__ biasf,
                                                   const float* __restrict__ biasb)
{
    extern __shared__ char smem[];
    const uint32_t sb = smem_u32(smem);
    const int tid = threadIdx.x;
    const int warp = tid >> 5, lane = tid & 31;
    const int by = blockIdx.x & 15;
    const int tb = blockIdx.x >> 4;
    const int bm = tb * 128;
    const int bn = by * 128;
    const int warp_m = (warp & 1) * 64;
    const int warp_n = (warp >> 1) * 32;

    const __nv_bfloat16* Ab = g_A2 + (size_t)bm * 3072;
    const __nv_bfloat16* Bb = g_W2 + (size_t)bn * 3072;

    float acc[4][4][4];
#pragma unroll
    for (int im = 0; im < 4; im++)
#pragma unroll
        for (int in = 0; in < 4; in++)
#pragma unroll
            for (int q = 0; q < 4; q++) acc[im][in][q] = 0.0f;

    const int aj = tid & 7;

    auto load_stage = [&](int c, int buf) {
        const int kb = c * 64;
        const uint32_t dA = sb + (buf ? SM_A1 : SM_A0);
        const uint32_t dB = sb + (buf ? SM_B1 : SM_B0);
#pragma unroll
        for (int i = 0; i < 4; i++) {
            int row = (tid + i * 256) >> 3;
            cp16(dA + SMEM_SWIZZLE_128B(row * 128 + aj * 16),
                 Ab + (size_t)row * 3072 + kb + aj * 8);
        }
#pragma unroll
        for (int i = 0; i < 4; i++) {
            int row = (tid + i * 256) >> 3;
            cp16(dB + SMEM_SWIZZLE_128B(row * 128 + aj * 16),
                 Bb + (size_t)row * 3072 + kb + aj * 8);
        }
        asm volatile("cp.async.commit_group;" ::: "memory");
    };

    load_stage(0, 0);

    for (int c = 0; c < NC; c++) {
        const int cur = c & 1;
        if (c + 1 < NC) {
            load_stage(c + 1, cur ^ 1);
            asm volatile("cp.async.wait_group 1;" ::: "memory");
        } else {
            asm volatile("cp.async.wait_group 0;" ::: "memory");
        }
        __syncthreads();

        const uint32_t aBase = sb + (cur ? SM_A1 : SM_A0);
        const uint32_t bBase = sb + (cur ? SM_B1 : SM_B0);
#pragma unroll
        for (int ks = 0; ks < 4; ks++) {
            uint32_t af[4][4];
#pragma unroll
            for (int im = 0; im < 4; im++) {
                int row = warp_m + im * 16 + (lane & 15);
                uint32_t addr = aBase + SMEM_SWIZZLE_128B(row * 128 + ks * 32 + ((lane >> 4) << 4));
                asm volatile("ldmatrix.sync.aligned.m8n8.x4.shared.b16 {%0,%1,%2,%3}, [%4];"
                    : "=r"(af[im][0]), "=r"(af[im][1]), "=r"(af[im][2]), "=r"(af[im][3])
                    : "r"(addr));
            }
            uint32_t bfr[4][2];
#pragma unroll
            for (int ib = 0; ib < 2; ib++) {
                int row = warp_n + ib * 16 + (lane & 7) + (((lane >> 4) & 1) << 3);
                uint32_t addr = bBase + SMEM_SWIZZLE_128B(row * 128 + ks * 32 + (((lane >> 3) & 1) << 4));
                asm volatile("ldmatrix.sync.aligned.m8n8.x4.shared.b16 {%0,%1,%2,%3}, [%4];"
                    : "=r"(bfr[2 * ib][0]), "=r"(bfr[2 * ib][1]),
                      "=r"(bfr[2 * ib + 1][0]), "=r"(bfr[2 * ib + 1][1])
                    : "r"(addr));
            }
#pragma unroll
            for (int im = 0; im < 4; im++)
#pragma unroll
                for (int in = 0; in < 4; in++) {
                    asm volatile(
                        "mma.sync.aligned.m16n8k16.row.col.f32.bf16.bf16.f32 "
                        "{%0,%1,%2,%3}, {%4,%5,%6,%7}, {%8,%9}, {%0,%1,%2,%3};"
                        : "+f"(acc[im][in][0]), "+f"(acc[im][in][1]),
                          "+f"(acc[im][in][2]), "+f"(acc[im][in][3])
                        : "r"(af[im][0]), "r"(af[im][1]), "r"(af[im][2]), "r"(af[im][3]),
                          "r"(bfr[in][0]), "r"(bfr[in][1]));
                }
        }
        __syncthreads();
    }

    const float* bp = (bn < 1024) ? (biasf + bn) : (biasb + (bn - 1024));
#pragma unroll
    for (int im = 0; im < 4; im++) {
        const int r0 = bm + warp_m + im * 16 + (lane >> 2);
#pragma unroll
        for (int in = 0; in < 4; in++) {
            const int cl = warp_n + in * 8 + (lane & 3) * 2;
            float bx = __ldg(bp + cl), by2 = __ldg(bp + cl + 1);
            float2 v0 = { acc[im][in][0] + bx, acc[im][in][1] + by2 };
            float2 v1 = { acc[im][in][2] + bx, acc[im][in][3] + by2 };
            *(float2*)(g_gx + (size_t)r0 * 2048 + bn + cl) = v0;
            *(float2*)(g_gx + (size_t)(r0 + 8) * 2048 + bn + cl) = v1;
        }
    }
}

// ---------------- Phase 2: persistent encoder (512 thr, warp-per-gate-row) --------
// 128 blocks x 512 threads. Warp w (0..15) owns gate row w of this block's 4 hidden
// dims; lane = batch. Weight load = warp-broadcast (free); h load conflict-free
// (stride 65 float4 == 4 mod 32 banks).
__global__ void __launch_bounds__(512) enc_persist(
    const float* __restrict__ WhhF, const float* __restrict__ WhhB)
{
    extern __shared__ float sm[];
    float* sW = sm;                  // [16][260]
    float* sH = sW + 16 * 260;       // [32][260]
    float* sG = sH + 32 * 260;       // [16][33]
    float* sC = sG + 16 * 33;        // [128]
    const int dir = blockIdx.x >> 6;
    const int j0  = (blockIdx.x & 63) * 4;
    const int tid = threadIdx.x;
    const float* Whh = dir ? WhhB : WhhF;

    for (int i = tid; i < 16 * 256; i += 512) {
        int r = i >> 8, k = i & 255;
        int row = (r >> 2) * 256 + j0 + (r & 3);
        sW[r * 260 + k] = Whh[row * 256 + k];
    }
    for (int i = tid; i < 32 * 260; i += 512) sH[i] = 0.0f;
    if (tid < 128) sC[tid] = 0.0f;
    __syncthreads();

    const int w = tid >> 5;          // gate row 0..15
    const int b = tid & 31;          // batch
    const int rowg = (w >> 2) * 256 + j0 + (w & 3);
    const float4* sH4 = (const float4*)sH;
    const float4* sW4 = (const float4*)sW;
    const int hbase4 = b * 65;
    const int wbase4 = w * 65;
    float* hout0 = g_h[0] + dir * (BB * HH);
    float* hout1 = g_h[1] + dir * (BB * HH);

    for (int t = 0; t < TT; t++) {
        const int teff = dir ? (TT - 1 - t) : t;
        float gx = g_gx[(size_t)teff * (BB * 2048) + (size_t)b * 2048 + dir * 1024 + rowg];
        float a = 0.0f;
#pragma unroll 16
        for (int k4 = 0; k4 < 64; k4++) {
            float4 hv = sH4[hbase4 + k4];
            float4 wv = sW4[wbase4 + k4];
            a += wv.x * hv.x + wv.y * hv.y + wv.z * hv.z + wv.w * hv.w;
        }
        sG[w * 33 + b] = a + gx;
        __syncthreads();
        float* hout = (t & 1) ? hout1 : hout0;
        if (tid < 128) {
            const int j = tid >> 5, bb = tid & 31;
            float gi = sG[(0 * 4 + j) * 33 + bb];
            float gf = sG[(1 * 4 + j) * 33 + bb];
            float gg = sG[(2 * 4 + j) * 33 + bb];
            float go = sG[(3 * 4 + j) * 33 + bb];
            float c  = sigf(gf) * sC[tid] + sigf(gi) * tanhf(gg);
            sC[tid] = c;
            hout[bb * 256 + j0 + j] = sigf(go) * tanhf(c);
        }
        gridbar_inc(dir, (unsigned)(t + 1) * 64u);
        const float4* src = (const float4*)hout;
        float4* dst4 = (float4*)sH;
        for (int i = tid; i < 32 * 64; i += 512) {
            int bb = i >> 6, kk = i & 63;
            dst4[bb * 65 + kk] = __ldcg(src + bb * 64 + kk);
        }
        __syncthreads();
    }
    if (tid < 128) {
        const int j = tid >> 5, bb = tid & 31;
        g_c[dir * (BB * HH) + bb * 256 + j0 + j] = sC[tid];
    }
}

// ---------------- Phase 3: persistent decoder (512 thr, warp-per-(row,matrix)) ----
// 128 blocks x 512 threads; block owns 2 hidden dims of BOTH layers. 16 warps:
// warps 0-7 compute the x-dot for gate rows 0-7, warps 8-15 the h-dot; partials
// combined in the activation. Lane = batch (conflict-free smem).
__global__ void __launch_bounds__(512) dec_persist(
    const float* __restrict__ Wih0, const float* __restrict__ Whh0, const float* __restrict__ b0v,
    const float* __restrict__ Wih1, const float* __restrict__ Whh1, const float* __restrict__ b1v,
    const float* __restrict__ linW, const float* __restrict__ linb,
    float* __restrict__ out)
{
    extern __shared__ float sm[];
    float* sWi0 = sm;                    // [8][260]
    float* sWh0 = sWi0 + 8 * 260;
    float* sWi1 = sWh0 + 8 * 260;
    float* sWh1 = sWi1 + 8 * 260;
    float* sX   = sWh1 + 8 * 260;        // [32][260]
    float* sH   = sX + 32 * 260;         // [32][260]
    float* sGp  = sH + 32 * 260;         // [2][8*33] partial sums (x-dot, h-dot)
    float* sC   = sGp + 2 * 8 * 33;      // [128]
    float* sB0  = sC + 128;              // [8]
    float* sB1  = sB0 + 8;               // [8]
    const int tid = threadIdx.x;
    const int j0 = blockIdx.x * 2;

    for (int i = tid; i < 8 * 256; i += 512) {
        int r = i >> 8, k = i & 255;
        int row = (r >> 1) * 256 + j0 + (r & 1);
        sWi0[r * 260 + k] = Wih0[row * 256 + k];
        sWh0[r * 260 + k] = Whh0[row * 256 + k];
        sWi1[r * 260 + k] = Wih1[row * 256 + k];
        sWh1[r * 260 + k] = Whh1[row * 256 + k];
    }
    if (tid < 64) {
        int d = tid >> 5, bb = tid & 31;
        sC[tid]      = g_c[bb * 256 + j0 + d];
        sC[64 + tid] = g_c[BB * HH + bb * 256 + j0 + d];
    }
    if (tid < 8) {
        int row = (tid >> 1) * 256 + j0 + (tid & 1);
        sB0[tid] = b0v[row];
        sB1[tid] = b1v[row];
    }
    __syncthreads();

    const float* hf = g_h[1];
    const float* hb = g_h[1] + BB * HH;
    const int w = tid >> 5;              // warp 0..15
    const int b = tid & 31;              // batch
    const int drow = w & 7;              // gate row 0..7
    const int dmat = w >> 3;             // 0 = x-dot, 1 = h-dot
    const float4* sX4 = (const float4*)sX;
    const float4* sH4 = (const float4*)sH;
    unsigned barcnt = 0;

    for (int t = 0; t < NSTEP; t++) {
        // ---- phase A: layer 0  (x = prev h1, h = prev h0) ----
        {
            float4* dX = (float4*)sX;
            float4* dH = (float4*)sH;
            const float4* srcX = (t == 0) ? (const float4*)0 : (const float4*)g_dh1[(t + 1) & 1];
            const float4* srcH = (t == 0) ? (const float4*)hf : (const float4*)g_dh0[(t + 1) & 1];
            for (int i = tid; i < 32 * 64; i += 512) {
                int bb = i >> 6, kk = i & 63;
                dX[bb * 65 + kk] = srcX ? __ldcg(srcX + bb * 64 + kk) : make_float4(0.f, 0.f, 0.f, 0.f);
                dH[bb * 65 + kk] = __ldcg(srcH + bb * 64 + kk);
            }
            __syncthreads();
            if (t > 0 && blockIdx.x == 0 && tid >= 256 && tid < 352) {  // y_{t-1} from sX
                int pt = tid - 256;
                int pb = pt / 3, pv = pt - pb * 3;
                float acc = linb[pv];
                const float* xr = sX + pb * 260;
                const float* wv = linW + pv * 256;
#pragma unroll 8
                for (int k = 0; k < 256; k++) acc += xr[k] * wv[k];
                out[(size_t)(t - 1) * 96 + pb * 3 + pv] = acc;
            }
            {
                const float4* wv4 = (const float4*)(dmat ? sWh0 : sWi0) + drow * 65;
                const float4* vv4 = (dmat ? sH4 : sX4) + b * 65;
                float a = 0.0f;
#pragma unroll 16
                for (int k4 = 0; k4 < 64; k4++) {
                    float4 vv = vv4[k4], wv = wv4[k4];
                    a += wv.x * vv.x + wv.y * vv.y + wv.z * vv.z + wv.w * vv.w;
                }
                sGp[dmat * 264 + drow * 33 + b] = a;
            }
            __syncthreads();
            if (tid < 64) {
                int d = tid >> 5, bb = tid & 31;
                float gi = sGp[(0 * 2 + d) * 33 + bb] + sGp[264 + (0 * 2 + d) * 33 + bb] + sB0[0 * 2 + d];
                float gf = sGp[(1 * 2 + d) * 33 + bb] + sGp[264 + (1 * 2 + d) * 33 + bb] + sB0[1 * 2 + d];
                float gg = sGp[(2 * 2 + d) * 33 + bb] + sGp[264 + (2 * 2 + d) * 33 + bb] + sB0[2 * 2 + d];
                float go = sGp[(3 * 2 + d) * 33 + bb] + sGp[264 + (3 * 2 + d) * 33 + bb] + sB0[3 * 2 + d];
                float c = sigf(gf) * sC[tid] + sigf(gi) * tanhf(gg);
                sC[tid] = c;
                g_dh0[t & 1][bb * 256 + j0 + d] = sigf(go) * tanhf(c);
            }
            barcnt++;
            gridbar_inc(2, barcnt * 128u);
        }
        // ---- phase B: layer 1  (x = new h0, h = prev h1) ----
        {
            float4* dX = (float4*)sX;
            float4* dH = (float4*)sH;
            const float4* srcX = (const float4*)g_dh0[t & 1];
            const float4* srcH = (t == 0) ? (const float4*)hb : (const float4*)g_dh1[(t + 1) & 1];
            for (int i = tid; i < 32 * 64; i += 512) {
                int bb = i >> 6, kk = i & 63;
                dX[bb * 65 + kk] = __ldcg(srcX + bb * 64 + kk);
                dH[bb * 65 + kk] = __ldcg(srcH + bb * 64 + kk);
            }
            __syncthreads();
            {
                const float4* wv4 = (const float4*)(dmat ? sWh1 : sWi1) + drow * 65;
                const float4* vv4 = (dmat ? sH4 : sX4) + b * 65;
                float a = 0.0f;
#pragma unroll 16
                for (int k4 = 0; k4 < 64; k4++) {
                    float4 vv = vv4[k4], wv = wv4[k4];
                    a += wv.x * vv.x + wv.y * vv.y + wv.z * vv.z + wv.w * vv.w;
                }
                sGp[dmat * 264 + drow * 33 + b] = a;
            }
            __syncthreads();
            if (tid < 64) {
                int d = tid >> 5, bb = tid & 31;
                float gi = sGp[(0 * 2 + d) * 33 + bb] + sGp[264 + (0 * 2 + d) * 33 + bb] + sB1[0 * 2 + d];
                float gf = sGp[(1 * 2 + d) * 33 + bb] + sGp[264 + (1 * 2 + d) * 33 + bb] + sB1[1 * 2 + d];
                float gg = sGp[(2 * 2 + d) * 33 + bb] + sGp[264 + (2 * 2 + d) * 33 + bb] + sB1[2 * 2 + d];
                float go = sGp[(3 * 2 + d) * 33 + bb] + sGp[264 + (3 * 2 + d) * 33 + bb] + sB1[3 * 2 + d];
                float c = sigf(gf) * sC[64 + tid] + sigf(gi) * tanhf(gg);
                sC[64 + tid] = c;
                g_dh1[t & 1][bb * 256 + j0 + d] = sigf(go) * tanhf(c);
            }
            barcnt++;
            gridbar_inc(2, barcnt * 128u);
        }
    }
    if (blockIdx.x == 0 && tid < 96) {
        int pb = tid / 3, pv = tid - pb * 3;
        float acc = linb[pv];
        const float* xr = g_dh1[(NSTEP - 1) & 1] + pb * 256;
        const float* wv = linW + pv * 256;
#pragma unroll 8
        for (int k = 0; k < 256; k++) acc += __ldcg(xr + k) * wv[k];
        out[(size_t)(NSTEP - 1) * 96 + pb * 3 + pv] = acc;
    }
}

// ---------------- launch ----------------
extern "C" void kernel_launch(void* const* d_in, const int* in_sizes, int n_in,
                              void* d_out, int out_size)
{
    (void)in_sizes; (void)n_in; (void)out_size;
    const float* cnn   = (const float*)d_in[0];
    const float* eWihF = (const float*)d_in[1];
    const float* eWhhF = (const float*)d_in[2];
    const float* ebF   = (const float*)d_in[3];
    const float* eWihB = (const float*)d_in[4];
    const float* eWhhB = (const float*)d_in[5];
    const float* ebB   = (const float*)d_in[6];
    const float* dWih0 = (const float*)d_in[7];
    const float* dWhh0 = (const float*)d_in[8];
    const float* db0   = (const float*)d_in[9];
    const float* dWih1 = (const float*)d_in[10];
    const float* dWhh1 = (const float*)d_in[11];
    const float* db1   = (const float*)d_in[12];
    const float* linW  = (const float*)d_in[13];
    const float* linb  = (const float*)d_in[14];
    float* out = (float*)d_out;

    const int enc_smem = (16 * 260 + 32 * 260 + 16 * 33 + 128) * 4;
    const int dec_smem = (4 * 8 * 260 + 2 * 32 * 260 + 2 * 8 * 33 + 128 + 16) * 4;
    cudaFuncSetAttribute(gemm_mma,    cudaFuncAttributeMaxDynamicSharedMemorySize, GEMM_SMEM);
    cudaFuncSetAttribute(enc_persist, cudaFuncAttributeMaxDynamicSharedMemorySize, enc_smem);
    cudaFuncSetAttribute(dec_persist, cudaFuncAttributeMaxDynamicSharedMemorySize, dec_smem);

    // reset monotonic barrier counters for this replay
    void* cntp = nullptr;
    cudaGetSymbolAddress(&cntp, g_cnt);
    cudaMemsetAsync(cntp, 0, 4 * sizeof(unsigned));

    // Phase 0: bf16 hi/lo splits of activations and both Wih matrices
    conv_a<<<16384, 256>>>(cnn);
    conv_w<<<2048, 256>>>(eWihF, eWihB);

    // Phase 1: HMMA bf16 3-term input-projection GEMM (128x128 tiles, 2 CTAs/SM)
    gemm_mma<<<2048, 256, GEMM_SMEM>>>(ebF, ebB);

    // Phase 2: entire encoder recurrence in one persistent launch
    enc_persist<<<128, 512, enc_smem>>>(eWhhF, eWhhB);

    // Phase 3: entire decoder + projections in one persistent launch
    dec_persist<<<128, 512, dec_smem>>>(dWih0, dWhh0, db0, dWih1, dWhh1, db1,
                                        linW, linb, out);
}